// round 12
// baseline (speedup 1.0000x reference)
#include <cuda_runtime.h>

#define N_POS 8192
#define N_NEG 4000
#define N_TOT (N_POS + N_POS * N_NEG)   // 32,776,192 = 8192*4001
#define NT4   (N_TOT / 4)               // 8,194,048 vec4 tiles

constexpr int TPB2 = 512;               // pass-2 block size (16 warps)
constexpr int NB2  = 296;               // pass-2 blocks (2/SM, 64KB smem each)
constexpr int NFB  = 64;                // finalize blocks

// Static scratch (allocations forbidden).
__device__ float        g_pos[N_POS];
__device__ unsigned int g_hist[NB2 * N_POS];   // per-block histograms, 9.7MB
__device__ float        g_psum[NFB];
__device__ unsigned int g_ticket;

// ---------------- Pass 1: scan index (131MB), scatter the 8192 pos values ----
// Coalesced: the q-th int4 load of a warp has consecutive lanes.
constexpr int TPB1  = 256;
constexpr int EPT1  = 32;                      // ints per thread (8 int4 loads)
constexpr int NBLK1 = N_TOT / (TPB1 * EPT1);   // 4001, exact

__global__ __launch_bounds__(TPB1) void k_scatter_pos(
    const int*   __restrict__ idx,
    const float* __restrict__ pv)
{
    const int4* idx4 = reinterpret_cast<const int4*>(idx);
    unsigned int base4 = blockIdx.x * (TPB1 * (EPT1 / 4));  // block's int4 base
    int4 r[8];
#pragma unroll
    for (int q = 0; q < 8; q++)
        r[q] = idx4[base4 + q * TPB1 + threadIdx.x];
#pragma unroll
    for (int q = 0; q < 8; q++) {
        unsigned int e0 = (base4 + q * TPB1 + threadIdx.x) * 4;
        int js[4] = {r[q].x, r[q].y, r[q].z, r[q].w};
#pragma unroll
        for (int k = 0; k < 4; k++) {
            unsigned int j = (unsigned int)js[k];
            if (j < N_POS) g_pos[j] = pv[e0 + k];   // rare: 8192/32.7M
        }
    }
    if (blockIdx.x == 0 && threadIdx.x == 0) g_ticket = 0u;
}

// ---------------- Pass 2: smem pos table + smem histograms -------------------
// Rarer-side counting: pos>0 -> count (v >  pos), rank = 1+cnt
//                      pos<=0-> count (v <= pos), rank = 4001-cnt
// Software-pipelined: 2 tiles in flight; batch loads -> gathers -> atomics.
__global__ __launch_bounds__(TPB2) void k_count(
    const int*   __restrict__ idx,
    const float* __restrict__ pv)
{
    __shared__ float        spos[N_POS];   // 32KB
    __shared__ unsigned int hist[N_POS];   // 32KB

    for (int i = threadIdx.x; i < N_POS; i += TPB2) {
        spos[i] = g_pos[i];                // coalesced table load
        hist[i] = 0u;
    }
    __syncthreads();

    const int4*   idx4 = reinterpret_cast<const int4*>(idx);
    const float4* pv4  = reinterpret_cast<const float4*>(pv);
    const unsigned int stride = NB2 * TPB2;

    for (unsigned int t = blockIdx.x * TPB2 + threadIdx.x; t < NT4; t += 2 * stride) {
        const unsigned int t1 = t + stride;
        const bool have2 = (t1 < NT4);

        // Phase 1: stream loads (max MLP)
        int4   a0 = idx4[t];
        float4 v0 = pv4[t];
        int4   a1; float4 v1;
        if (have2) { a1 = idx4[t1]; v1 = pv4[t1]; }
        else { a1 = make_int4(0,0,0,0); v1 = make_float4(0,0,0,0); }

        int   js[8] = {a0.x, a0.y, a0.z, a0.w, a1.x, a1.y, a1.z, a1.w};
        float vs[8] = {v0.x, v0.y, v0.z, v0.w, v1.x, v1.y, v1.z, v1.w};

        // Phase 2: indices + batched LDS gathers
        unsigned int p[8];
        float        pos[8];
        bool         neg[8];
#pragma unroll
        for (int k = 0; k < 8; k++) {
            unsigned int j = (unsigned int)js[k];
            bool valid = (k < 4) | have2;
            neg[k] = valid && (j >= N_POS);
            p[k]   = neg[k] ? (j - N_POS) / N_NEG : 0u;   // umulhi
            pos[k] = spos[p[k]];                           // LDS (harmless if !neg)
        }

        // Phase 3: predicated ATOMS burst
#pragma unroll
        for (int k = 0; k < 8; k++) {
            if (neg[k] && ((vs[k] > pos[k]) == (pos[k] > 0.0f))) {
                atomicAdd(&hist[p[k]], 1u);                // ATOMS, spread-addr
            }
        }
    }
    __syncthreads();

    unsigned int* row = g_hist + (size_t)blockIdx.x * N_POS;
    for (int i = threadIdx.x; i < N_POS; i += TPB2) row[i] = hist[i];  // coalesced
}

// ---------------- Finalize: reduce hists, smrr, deterministic mean -----------
__global__ __launch_bounds__(128) void k_final(float* __restrict__ out)
{
    int p = blockIdx.x * 128 + threadIdx.x;   // 64 x 128 = 8192
    unsigned int cnt = 0;
#pragma unroll 4
    for (int b = 0; b < NB2; b++)
        cnt += g_hist[(size_t)b * N_POS + p]; // coalesced across threads

    float pos = g_pos[p];
    unsigned int rank = (pos > 0.0f) ? (1u + cnt)
                                     : (unsigned int)(N_NEG + 1) - cnt;
    float smrr = 1.0f / (float)rank;
    out[1 + p] = smrr;

    __shared__ float ssum[128];
    ssum[threadIdx.x] = smrr;
    __syncthreads();
    for (int off = 64; off > 0; off >>= 1) {
        if (threadIdx.x < off) ssum[threadIdx.x] += ssum[threadIdx.x + off];
        __syncthreads();
    }
    __shared__ bool last;
    if (threadIdx.x == 0) {
        g_psum[blockIdx.x] = ssum[0];
        __threadfence();
        last = (atomicAdd(&g_ticket, 1u) == NFB - 1);
    }
    __syncthreads();
    if (last && threadIdx.x == 0) {
        float s = 0.0f;
        for (int i = 0; i < NFB; i++) s += g_psum[i];
        out[0] = s / (float)N_POS;
    }
}

extern "C" void kernel_launch(void* const* d_in, const int* in_sizes, int n_in,
                              void* d_out, int out_size)
{
    const float* pv  = (const float*)d_in[0];
    const int*   idx = (const int*)d_in[1];
    float* out = (float*)d_out;
    (void)in_sizes; (void)n_in; (void)out_size;

    k_scatter_pos<<<NBLK1, TPB1>>>(idx, pv);
    k_count<<<NB2, TPB2>>>(idx, pv);
    k_final<<<NFB, 128>>>(out);
}

// round 13
// speedup vs baseline: 1.3616x; 1.3616x over previous
#include <cuda_runtime.h>

#define N_POS 8192
#define N_NEG 4000
#define N_TOT (N_POS + N_POS * N_NEG)   // 32,776,192 = 8192*4001
#define NT4   (N_TOT / 4)               // 8,194,048 vec4 tiles

constexpr int TPB2 = 512;               // pass-2 block size (16 warps)
constexpr int NB2  = 296;               // pass-2 blocks (2/SM, 64KB smem each)
constexpr int NFB  = 64;                // finalize blocks

// Static scratch (allocations forbidden).
__device__ float        g_pos[N_POS];
__device__ unsigned int g_hist[NB2 * N_POS];   // per-block histograms, 9.7MB
__device__ float        g_psum[NFB];
__device__ unsigned int g_ticket;

// ---------------- Pass 1: scan index (131MB), scatter the 8192 pos values ----
// Coalesced: the q-th int4 load of a warp has consecutive lanes. idx reads use
// the default cache policy ON PURPOSE: pass 2 re-reads idx (reversed) and we
// want the tail of idx resident in L2.
constexpr int TPB1  = 256;
constexpr int EPT1  = 32;                      // ints per thread (8 int4 loads)
constexpr int NBLK1 = N_TOT / (TPB1 * EPT1);   // 4001, exact

__global__ __launch_bounds__(TPB1) void k_scatter_pos(
    const int*   __restrict__ idx,
    const float* __restrict__ pv)
{
    const int4* idx4 = reinterpret_cast<const int4*>(idx);
    unsigned int base4 = blockIdx.x * (TPB1 * (EPT1 / 4));  // block's int4 base
    int4 r[8];
#pragma unroll
    for (int q = 0; q < 8; q++)
        r[q] = idx4[base4 + q * TPB1 + threadIdx.x];
#pragma unroll
    for (int q = 0; q < 8; q++) {
        unsigned int e0 = (base4 + q * TPB1 + threadIdx.x) * 4;
        int js[4] = {r[q].x, r[q].y, r[q].z, r[q].w};
#pragma unroll
        for (int k = 0; k < 4; k++) {
            unsigned int j = (unsigned int)js[k];
            if (j < N_POS) g_pos[j] = pv[e0 + k];   // rare: 8192/32.7M
        }
    }
    if (blockIdx.x == 0 && threadIdx.x == 0) g_ticket = 0u;
}

// ---------------- Pass 2: smem pos table + smem histograms -------------------
// Rarer-side counting: pos>0 -> count (v >  pos), rank = 1+cnt
//                      pos<=0-> count (v <= pos), rank = 4001-cnt
// REVERSED traversal: pass 1 streamed idx low->high, so L2 holds the tail of
// idx; reading high->low turns a large fraction of idx reads into L2 hits.
__global__ __launch_bounds__(TPB2) void k_count(
    const int*   __restrict__ idx,
    const float* __restrict__ pv)
{
    __shared__ float        spos[N_POS];   // 32KB
    __shared__ unsigned int hist[N_POS];   // 32KB

    for (int i = threadIdx.x; i < N_POS; i += TPB2) {
        spos[i] = g_pos[i];                // coalesced table load
        hist[i] = 0u;
    }
    __syncthreads();

    const int4*   idx4 = reinterpret_cast<const int4*>(idx);
    const float4* pv4  = reinterpret_cast<const float4*>(pv);

    for (unsigned int u = blockIdx.x * TPB2 + threadIdx.x; u < NT4; u += NB2 * TPB2) {
        const unsigned int t = (NT4 - 1u) - u;           // reversed, coalesced
        int4   a = __ldcs(&idx4[t]);                     // last use of idx
        float4 v = __ldcs(&pv4[t]);                      // single use of pv
        int   js[4] = {a.x, a.y, a.z, a.w};
        float vs[4] = {v.x, v.y, v.z, v.w};
#pragma unroll
        for (int k = 0; k < 4; k++) {
            unsigned int j = (unsigned int)js[k];
            if (j >= N_POS) {
                unsigned int p = (j - N_POS) / N_NEG;   // const-div -> umulhi
                float pos = spos[p];                     // LDS (predicated)
                if ((vs[k] > pos) == (pos > 0.0f)) {     // rarer side (~25%)
                    atomicAdd(&hist[p], 1u);             // ATOMS, spread-addr
                }
            }
        }
    }
    __syncthreads();

    unsigned int* row = g_hist + (size_t)blockIdx.x * N_POS;
    for (int i = threadIdx.x; i < N_POS; i += TPB2) row[i] = hist[i];  // coalesced
}

// ---------------- Finalize: reduce hists, smrr, deterministic mean -----------
__global__ __launch_bounds__(128) void k_final(float* __restrict__ out)
{
    int p = blockIdx.x * 128 + threadIdx.x;   // 64 x 128 = 8192
    unsigned int cnt = 0;
#pragma unroll 4
    for (int b = 0; b < NB2; b++)
        cnt += g_hist[(size_t)b * N_POS + p]; // coalesced across threads

    float pos = g_pos[p];
    unsigned int rank = (pos > 0.0f) ? (1u + cnt)
                                     : (unsigned int)(N_NEG + 1) - cnt;
    float smrr = 1.0f / (float)rank;
    out[1 + p] = smrr;

    __shared__ float ssum[128];
    ssum[threadIdx.x] = smrr;
    __syncthreads();
    for (int off = 64; off > 0; off >>= 1) {
        if (threadIdx.x < off) ssum[threadIdx.x] += ssum[threadIdx.x + off];
        __syncthreads();
    }
    __shared__ bool last;
    if (threadIdx.x == 0) {
        g_psum[blockIdx.x] = ssum[0];
        __threadfence();
        last = (atomicAdd(&g_ticket, 1u) == NFB - 1);
    }
    __syncthreads();
    if (last && threadIdx.x == 0) {
        float s = 0.0f;
        for (int i = 0; i < NFB; i++) s += g_psum[i];
        out[0] = s / (float)N_POS;
    }
}

extern "C" void kernel_launch(void* const* d_in, const int* in_sizes, int n_in,
                              void* d_out, int out_size)
{
    const float* pv  = (const float*)d_in[0];
    const int*   idx = (const int*)d_in[1];
    float* out = (float*)d_out;
    (void)in_sizes; (void)n_in; (void)out_size;

    k_scatter_pos<<<NBLK1, TPB1>>>(idx, pv);
    k_count<<<NB2, TPB2>>>(idx, pv);
    k_final<<<NFB, 128>>>(out);
}